// round 16
// baseline (speedup 1.0000x reference)
#include <cuda_runtime.h>
#include <cuda_fp16.h>
#include <float.h>

// features: [B=8, X=128, Y=128, C=128] f32   (C contiguous)
// rois:     [B, N=128, 4] i32  (minX, minY, maxX, maxY)
// out:      [B, N, 7, 7, C] f32
//
// FUSED persistent kernel, per-batch pipelined:
//   Stage 1: P1[b][x][y][c] = (half)max 2x2 window (4x4 tiles, reg-carried),
//            batch-major tile order; warp bumps cnt[b] per finished tile.
//   Stage 2: bin (>=2x2) = max over P1 stride-2 samples clamped to edge-2
//            (R12-verified loop); a warp waits for cnt[b]==1024 before its
//            first batch-b bin. Both orders batch-ascending -> deep overlap:
//            stage2 L2 reads of batch b hide stage1 DRAM reads of b+1..7.

#define PH 7
#define PW 7
#define B_ 8
#define N_ 128
#define XDIM 128
#define YDIM 128
#define C4   32                  // 32 channel-quarters per pixel (4 ch each)
#define COLS (YDIM * C4)         // stride (in quarters) for +1 in x (4096)

#define NBLOCKS 256              // <= 148 SMs x 2 co-resident CTAs (296 cap)
#define NTHREADS 512
#define NWARPS (NBLOCKS * (NTHREADS / 32))   // 4096

#define P1_TILES (B_ * 32 * 32)              // 8192 warp-tiles: exactly 2/warp
#define TILES_PER_B (32 * 32)                // 1024
#define P2_BINS  (B_ * N_ * PH * PW)         // 50176
#define BINS_PER_B (N_ * PH * PW)            // 6272

// 32 MB scratch: [b][x][y][c4] half4 stored as uint2
__device__ uint2 d_P1[B_ * XDIM * YDIM * C4];
__device__ unsigned d_cnt[B_];

__device__ __forceinline__ float4 f4max(float4 a, float4 b) {
    return make_float4(fmaxf(a.x, b.x), fmaxf(a.y, b.y),
                       fmaxf(a.z, b.z), fmaxf(a.w, b.w));
}

__device__ __forceinline__ uint2 f4_to_h4(float4 v) {
    __half2 h01 = __floats2half2_rn(v.x, v.y);
    __half2 h23 = __floats2half2_rn(v.z, v.w);
    uint2 u;
    u.x = *reinterpret_cast<unsigned*>(&h01);
    u.y = *reinterpret_cast<unsigned*>(&h23);
    return u;
}

__device__ __forceinline__ void h4acc(uint2 v, __half2& a, __half2& b) {
    a = __hmax2(a, *reinterpret_cast<__half2*>(&v.x));
    b = __hmax2(b, *reinterpret_cast<__half2*>(&v.y));
}

// ---------------- Stage 1 tile: 4x4 outputs from 5x5 inputs ----------------
__device__ __forceinline__ void p1_tile(const float4* __restrict__ f, int tile,
                                        int lane)
{
    int yc = tile & 31;          // 32 y-chunks of 4
    int t  = tile >> 5;
    int xg = t & 31;             // 32 x-groups of 4
    int b  = t >> 5;
    int y0 = yc * 4;
    int x0 = xg * 4;

    const float4* p0 = f + (b * XDIM + x0) * COLS + y0 * C4 + lane;
    const float4* p1 = p0 + COLS;
    const float4* p2 = p1 + COLS;
    const float4* p3 = p2 + COLS;
    // row x0+4 clamped to 127 (only xg==31; junk output never read by stage 2)
    const float4* p4 = f + (b * XDIM + min(x0 + 4, XDIM - 1)) * COLS + y0 * C4 + lane;

    uint2* o = d_P1 + (b * XDIM + x0) * COLS + y0 * C4 + lane;

    int ymax = (YDIM - 1) - y0;  // clamp next-row load offset to y=127

    float4 c0 = p0[0], c1 = p1[0], c2 = p2[0], c3 = p3[0], c4 = p4[0];

    #pragma unroll
    for (int i = 0; i < 4; ++i) {
        int off = min(i + 1, ymax) * C4;
        float4 n0 = p0[off];
        float4 n1 = p1[off];
        float4 n2 = p2[off];
        float4 n3 = p3[off];
        float4 n4 = p4[off];
        o[0 * COLS + i * C4] = f4_to_h4(f4max(f4max(c0, c1), f4max(n0, n1)));
        o[1 * COLS + i * C4] = f4_to_h4(f4max(f4max(c1, c2), f4max(n1, n2)));
        o[2 * COLS + i * C4] = f4_to_h4(f4max(f4max(c2, c3), f4max(n2, n3)));
        o[3 * COLS + i * C4] = f4_to_h4(f4max(f4max(c3, c4), f4max(n3, n4)));
        c0 = n0; c1 = n1; c2 = n2; c3 = n3; c4 = n4;
    }
}

// ---------------- Stage 2 bin: R12-verified inner loop ----------------
__device__ __forceinline__ void p2_bin(const int4* __restrict__ rois, int u,
                                       int b, int lane,
                                       float4* __restrict__ out)
{
    int w = u % PW;
    int s = u / PW;
    int h = s % PH;
    int t = s / PH;               // t = b*N_ + n

    const int4 r = rois[t];
    int dx = (r.z - r.x) / PW;
    int dy = (r.w - r.y) / PH;

    int y0 = r.y + h * dy;
    int ny = (h == PH - 1) ? (r.w - y0) : dy;    // >= 2
    int x0 = r.x + w * dx;
    int nx = (w == PW - 1) ? (r.z - x0) : dx;    // >= 2

    int cx = (nx + 1) >> 1;
    int cy = (ny + 1) >> 1;
    int xle = (nx - 2) * COLS;    // clamp: last x sample = x1-2
    int yle = (ny - 2) * C4;      // clamp: last y sample = y1-2

    const uint2* base = d_P1 + (b * XDIM + x0) * COLS + y0 * C4 + lane;

    const __half2 NEG = __float2half2_rn(-65504.0f);
    __half2 m0 = NEG, m1 = NEG;
    __half2 m2 = NEG, m3 = NEG;

    int j = 0;
    for (; j + 2 <= cx; j += 2) {                 // two sample-columns at once
        const uint2* pA = base + min(2 * j * COLS, xle);
        const uint2* pB = base + min((2 * j + 2) * COLS, xle);
        int i = 0;
        for (; i + 2 <= cy; i += 2) {
            uint2 a0 = pA[min(2 * i * C4, yle)];
            uint2 a1 = pA[min((2 * i + 2) * C4, yle)];
            uint2 b0 = pB[min(2 * i * C4, yle)];
            uint2 b1 = pB[min((2 * i + 2) * C4, yle)];
            h4acc(a0, m0, m1);
            h4acc(a1, m2, m3);
            h4acc(b0, m0, m1);
            h4acc(b1, m2, m3);
        }
        if (i < cy) {
            int yo = min(2 * i * C4, yle);
            h4acc(pA[yo], m0, m1);
            h4acc(pB[yo], m2, m3);
        }
    }
    if (j < cx) {                                  // last single sample-column
        const uint2* pA = base + min(2 * j * COLS, xle);
        int i = 0;
        for (; i + 2 <= cy; i += 2) {
            uint2 a0 = pA[min(2 * i * C4, yle)];
            uint2 a1 = pA[min((2 * i + 2) * C4, yle)];
            h4acc(a0, m0, m1);
            h4acc(a1, m2, m3);
        }
        if (i < cy) {
            h4acc(pA[min(2 * i * C4, yle)], m0, m1);
        }
    }

    __half2 r01 = __hmax2(m0, m2);
    __half2 r23 = __hmax2(m1, m3);
    float2 lo = __half22float2(r01);
    float2 hi = __half22float2(r23);
    out[u * C4 + lane] = make_float4(lo.x, lo.y, hi.x, hi.y);
}

// ---------------- fused pipelined kernel ----------------
__global__ __launch_bounds__(NTHREADS, 2)
void roi_fused_kernel(const float4* __restrict__ features,
                      const int4*   __restrict__ rois,
                      float4*       __restrict__ out)
{
    int wid   = threadIdx.x >> 5;
    int lane  = threadIdx.x & 31;
    int gwarp = blockIdx.x * (NTHREADS / 32) + wid;

    // ---- Stage 1: build P1, signaling per-batch completion ----
    #pragma unroll
    for (int k = 0; k < P1_TILES / NWARPS; ++k) {       // exactly 2 tiles/warp
        int tile = gwarp + k * NWARPS;                   // batch-major order
        p1_tile(features, tile, lane);
        __threadfence();                                 // release P1 stores
        if (lane == 0)
            atomicAdd(&d_cnt[tile / TILES_PER_B], 1u);
    }

    // ---- Stage 2: pool bins, waiting per batch (monotone, batch-ascending) ----
    int ready = -1;
    for (int u = gwarp; u < P2_BINS; u += NWARPS) {
        int b = u / BINS_PER_B;
        if (b > ready) {
            if (lane == 0) {
                while (*(volatile unsigned*)&d_cnt[b] < (unsigned)TILES_PER_B)
                    __nanosleep(64);
            }
            __syncwarp();
            __threadfence();                             // acquire P1 loads
            ready = b;
        }
        p2_bin(rois, u, b, lane, out);
    }
}

extern "C" void kernel_launch(void* const* d_in, const int* in_sizes, int n_in,
                              void* d_out, int out_size)
{
    const float4* features = (const float4*)d_in[0];
    const int4*   rois     = (const int4*)d_in[1];
    float4*       out      = (float4*)d_out;

    // zero the per-batch counters (capturable async memset, no allocation)
    void* cnt_ptr = nullptr;
    cudaGetSymbolAddress(&cnt_ptr, d_cnt);
    cudaMemsetAsync(cnt_ptr, 0, B_ * sizeof(unsigned));

    roi_fused_kernel<<<NBLOCKS, NTHREADS>>>(features, rois, out);
}

// round 17
// speedup vs baseline: 1.1792x; 1.1792x over previous
#include <cuda_runtime.h>
#include <cuda_fp16.h>
#include <float.h>

// features: [B=8, X=128, Y=128, C=128] f32   (C contiguous)
// rois:     [B, N=128, 4] i32  (minX, minY, maxX, maxY)
// out:      [B, N, 7, 7, C] f32
//
// FUSED persistent kernel (R15 structure, verified):
//   Stage 1: P1[b][x][y][c] = (half)max 2x2 window of features (4x4 tiles,
//            register-carried rows), grid-strided over 8192 warp-tiles.
//   ---- single software grid barrier (all CTAs co-resident) ----
//   Stage 2: bin (>=2x2) = max over P1 at stride-2 samples clamped to
//            edge-2. NEW: y-dimension flattened to 4 clamped loads per
//            column (cy<=4 for most bins; duplicates idempotent) -> one
//            L2 round trip per 2-column batch instead of a nested loop.

#define PH 7
#define PW 7
#define B_ 8
#define N_ 128
#define XDIM 128
#define YDIM 128
#define C4   32                  // 32 channel-quarters per pixel (4 ch each)
#define COLS (YDIM * C4)         // stride (in quarters) for +1 in x (4096)

#define NBLOCKS 296              // 148 SMs x 2 co-resident CTAs
#define NTHREADS 512
#define NWARPS (NBLOCKS * (NTHREADS / 32))   // 4736

#define P1_TILES (B_ * 32 * 32)              // 8192 warp-tiles (4x4 each)
#define P2_BINS  (B_ * N_ * PH * PW)         // 50176 warp-bins

// 32 MB scratch: [b][x][y][c4] half4 stored as uint2
__device__ uint2 d_P1[B_ * XDIM * YDIM * C4];
__device__ unsigned d_bar;

__device__ __forceinline__ float4 f4max(float4 a, float4 b) {
    return make_float4(fmaxf(a.x, b.x), fmaxf(a.y, b.y),
                       fmaxf(a.z, b.z), fmaxf(a.w, b.w));
}

__device__ __forceinline__ uint2 f4_to_h4(float4 v) {
    __half2 h01 = __floats2half2_rn(v.x, v.y);
    __half2 h23 = __floats2half2_rn(v.z, v.w);
    uint2 u;
    u.x = *reinterpret_cast<unsigned*>(&h01);
    u.y = *reinterpret_cast<unsigned*>(&h23);
    return u;
}

__device__ __forceinline__ void h4acc(uint2 v, __half2& a, __half2& b) {
    a = __hmax2(a, *reinterpret_cast<__half2*>(&v.x));
    b = __hmax2(b, *reinterpret_cast<__half2*>(&v.y));
}

// ---------------- Stage 1 tile: 4x4 outputs from 5x5 inputs ----------------
__device__ __forceinline__ void p1_tile(const float4* __restrict__ f, int tile,
                                        int lane)
{
    int yc = tile & 31;          // 32 y-chunks of 4
    int t  = tile >> 5;
    int xg = t & 31;             // 32 x-groups of 4
    int b  = t >> 5;
    int y0 = yc * 4;
    int x0 = xg * 4;

    const float4* p0 = f + (b * XDIM + x0) * COLS + y0 * C4 + lane;
    const float4* p1 = p0 + COLS;
    const float4* p2 = p1 + COLS;
    const float4* p3 = p2 + COLS;
    // row x0+4 clamped to 127 (only xg==31; junk output never read by stage 2)
    const float4* p4 = f + (b * XDIM + min(x0 + 4, XDIM - 1)) * COLS + y0 * C4 + lane;

    uint2* o = d_P1 + (b * XDIM + x0) * COLS + y0 * C4 + lane;

    int ymax = (YDIM - 1) - y0;  // clamp next-row load offset to y=127

    float4 c0 = p0[0], c1 = p1[0], c2 = p2[0], c3 = p3[0], c4 = p4[0];

    #pragma unroll
    for (int i = 0; i < 4; ++i) {
        int off = min(i + 1, ymax) * C4;
        float4 n0 = p0[off];
        float4 n1 = p1[off];
        float4 n2 = p2[off];
        float4 n3 = p3[off];
        float4 n4 = p4[off];
        o[0 * COLS + i * C4] = f4_to_h4(f4max(f4max(c0, c1), f4max(n0, n1)));
        o[1 * COLS + i * C4] = f4_to_h4(f4max(f4max(c1, c2), f4max(n1, n2)));
        o[2 * COLS + i * C4] = f4_to_h4(f4max(f4max(c2, c3), f4max(n2, n3)));
        o[3 * COLS + i * C4] = f4_to_h4(f4max(f4max(c3, c4), f4max(n3, n4)));
        c0 = n0; c1 = n1; c2 = n2; c3 = n3; c4 = n4;
    }
}

// ---------------- Stage 2 bin: flat 4-clamped-y-loads per column ------------
__device__ __forceinline__ void p2_bin(const int4* __restrict__ rois, int u,
                                       int lane, float4* __restrict__ out)
{
    int w = u % PW;
    int s = u / PW;
    int h = s % PH;
    int t = s / PH;               // t = b*N_ + n
    int b = t >> 7;               // / N_

    const int4 r = rois[t];
    int dx = (r.z - r.x) / PW;
    int dy = (r.w - r.y) / PH;

    int y0 = r.y + h * dy;
    int ny = (h == PH - 1) ? (r.w - y0) : dy;    // >= 2
    int x0 = r.x + w * dx;
    int nx = (w == PW - 1) ? (r.z - x0) : dx;    // >= 2

    int cx  = (nx + 1) >> 1;      // sample columns (<= 8)
    int cy  = (ny + 1) >> 1;      // sample rows    (<= 8; <= 4 for ~6/7 bins)
    int xle = (nx - 2) * COLS;    // clamp: last x sample offset
    int yle = (ny - 2) * C4;      // clamp: last y sample offset

    const uint2* base = d_P1 + (b * XDIM + x0) * COLS + y0 * C4 + lane;

    // 4 clamped y offsets cover cy<=4 (duplicates are idempotent under max)
    int yo1 = min(2 * C4, yle);
    int yo2 = min(4 * C4, yle);
    int yo3 = min(6 * C4, yle);

    const __half2 NEG = __float2half2_rn(-65504.0f);
    __half2 m0 = NEG, m1 = NEG;
    __half2 m2 = NEG, m3 = NEG;

    int jj = 0;
    for (; jj + 2 <= cx; jj += 2) {       // 8 independent loads per iteration
        const uint2* pA = base + min((2 * jj)     * COLS, xle);
        const uint2* pB = base + min((2 * jj + 2) * COLS, xle);
        uint2 a0 = pA[0],   a1 = pA[yo1], a2 = pA[yo2], a3 = pA[yo3];
        uint2 b0 = pB[0],   b1 = pB[yo1], b2 = pB[yo2], b3 = pB[yo3];
        h4acc(a0, m0, m1); h4acc(a1, m2, m3);
        h4acc(a2, m0, m1); h4acc(a3, m2, m3);
        h4acc(b0, m0, m1); h4acc(b1, m2, m3);
        h4acc(b2, m0, m1); h4acc(b3, m2, m3);
    }
    if (jj < cx) {                         // last single column
        const uint2* pA = base + min((2 * jj) * COLS, xle);
        uint2 a0 = pA[0],   a1 = pA[yo1], a2 = pA[yo2], a3 = pA[yo3];
        h4acc(a0, m0, m1); h4acc(a1, m2, m3);
        h4acc(a2, m0, m1); h4acc(a3, m2, m3);
    }
    if (cy > 4) {                          // minority: ny in (8,15] (last-h bins)
        int yo4 = min(8  * C4, yle);
        int yo5 = min(10 * C4, yle);
        int yo6 = min(12 * C4, yle);
        int yo7 = min(14 * C4, yle);
        for (int j2 = 0; j2 < cx; ++j2) {
            const uint2* pA = base + min((2 * j2) * COLS, xle);
            uint2 a0 = pA[yo4], a1 = pA[yo5], a2 = pA[yo6], a3 = pA[yo7];
            h4acc(a0, m0, m1); h4acc(a1, m2, m3);
            h4acc(a2, m0, m1); h4acc(a3, m2, m3);
        }
    }

    __half2 r01 = __hmax2(m0, m2);
    __half2 r23 = __hmax2(m1, m3);
    float2 lo = __half22float2(r01);
    float2 hi = __half22float2(r23);
    out[u * C4 + lane] = make_float4(lo.x, lo.y, hi.x, hi.y);
}

// ---------------- fused persistent kernel ----------------
__global__ __launch_bounds__(NTHREADS, 2)
void roi_fused_kernel(const float4* __restrict__ features,
                      const int4*   __restrict__ rois,
                      float4*       __restrict__ out)
{
    int wid  = threadIdx.x >> 5;
    int lane = threadIdx.x & 31;
    int gwarp = blockIdx.x * (NTHREADS / 32) + wid;

    // ---- Stage 1: build P1 ----
    for (int tile = gwarp; tile < P1_TILES; tile += NWARPS)
        p1_tile(features, tile, lane);

    // ---- grid barrier (all NBLOCKS CTAs co-resident: 2 per SM guaranteed) ----
    __threadfence();              // make P1 stores visible GPU-wide
    __syncthreads();
    if (threadIdx.x == 0) {
        atomicAdd(&d_bar, 1u);
        while (atomicAdd(&d_bar, 0u) < (unsigned)gridDim.x)
            __nanosleep(64);
    }
    __syncthreads();
    __threadfence();              // order P1 loads after the barrier

    // ---- Stage 2: pool bins from P1 ----
    for (int u = gwarp; u < P2_BINS; u += NWARPS)
        p2_bin(rois, u, lane, out);
}

extern "C" void kernel_launch(void* const* d_in, const int* in_sizes, int n_in,
                              void* d_out, int out_size)
{
    const float4* features = (const float4*)d_in[0];
    const int4*   rois     = (const int4*)d_in[1];
    float4*       out      = (float4*)d_out;

    // zero the barrier counter (capturable async memset, no allocation)
    void* bar_ptr = nullptr;
    cudaGetSymbolAddress(&bar_ptr, d_bar);
    cudaMemsetAsync(bar_ptr, 0, sizeof(unsigned));

    roi_fused_kernel<<<NBLOCKS, NTHREADS>>>(features, rois, out);
}